// round 1
// baseline (speedup 1.0000x reference)
#include <cuda_runtime.h>

// LatticeCNN on GB300 — closed-form lattice conv decomposition.
//
// join conv  == pointwise with 2-D prefix-summed weights
// meet conv  == pointwise(suffix weights) + x-prefix row strips + y-prefix col
//               strips + 2-D-prefix corner term
//
// Per layer: 1521 GEMM units [64 x Fin] * [Fin x 128] + elementwise prefixes.

#define ALPHA  0.5f
#define SLOPE  0.01f
#define BATCH  64
#define S      32
#define NPIX   1024
#define FOUT   128

// ---------------- device scratch (no allocation allowed) ----------------
__device__ float d_Xt0[NPIX * BATCH * 64];    // layer0 input, pixel-major
__device__ float d_Yt [NPIX * BATCH * 128];   // layer0 output / layer1 input
__device__ float d_Yt2[NPIX * BATCH * 128];   // layer1 output (pixel-major)
__device__ float d_WC [225 * 128 * FOUT];     // combined pointwise weights (15x15 classes)
__device__ float d_MRS[64 * 128 * FOUT];      // row-suffix weights  MRS[a][q]
__device__ float d_MCS[64 * 128 * FOUT];      // col-suffix weights  MCS[p][b]
__device__ float d_G  [224 * BATCH * FOUT];   // row strip tiles  G[a][y]
__device__ float d_CG [224 * BATCH * FOUT];   // col strip tiles  CG[b][x]
__device__ float d_H  [49  * BATCH * FOUT];   // corner tiles     H[a][b]

// ---------------- tiled transpose: dst[C][R] = src[R][C] ----------------
__global__ void transpose_k(float* __restrict__ dst, const float* __restrict__ src,
                            int R, int C)
{
    __shared__ float tile[32][33];
    int c0 = blockIdx.x * 32;
    int r0 = blockIdx.y * 32;
    #pragma unroll
    for (int i = 0; i < 4; i++)
        tile[threadIdx.y + 8 * i][threadIdx.x] =
            src[(size_t)(r0 + threadIdx.y + 8 * i) * C + c0 + threadIdx.x];
    __syncthreads();
    #pragma unroll
    for (int i = 0; i < 4; i++)
        dst[(size_t)(c0 + threadIdx.y + 8 * i) * R + r0 + threadIdx.x] =
            tile[threadIdx.x][threadIdx.y + 8 * i];
}

// ---------------- per-layer weight-table prep ----------------
// thread per (f,g): builds suffix/prefix tables and the 15x15 class table.
__global__ void prep_k(const float* __restrict__ mw, const float* __restrict__ jw,
                       float* __restrict__ WC, float* __restrict__ MRS,
                       float* __restrict__ MCS, int Fin)
{
    int idx = blockIdx.x * blockDim.x + threadIdx.x;
    if (idx >= Fin * FOUT) return;
    int base = idx;              // = f*FOUT + g
    int ss = Fin * FOUT;

    float m[8][8];
    #pragma unroll
    for (int a = 0; a < 8; a++)
        #pragma unroll
        for (int b = 0; b < 8; b++)
            m[a][b] = mw[(a * 8 + b) * ss + base];

    // MCS[p][b] = sum_{a>=p} mw[a][b]
    {
        float col[8];
        #pragma unroll
        for (int b = 0; b < 8; b++) col[b] = 0.f;
        #pragma unroll
        for (int p = 7; p >= 0; p--)
            #pragma unroll
            for (int b = 0; b < 8; b++) {
                col[b] += m[p][b];
                MCS[(p * 8 + b) * ss + base] = col[b];
            }
    }
    // row suffix in place -> MRS[a][q] = sum_{b>=q} mw[a][b]
    #pragma unroll
    for (int a = 0; a < 8; a++) {
        #pragma unroll
        for (int q = 6; q >= 0; q--) m[a][q] += m[a][q + 1];
        #pragma unroll
        for (int q = 0; q < 8; q++) MRS[(a * 8 + q) * ss + base] = m[a][q];
    }
    // col suffix in place -> m = MS 2-D suffix table
    #pragma unroll
    for (int b = 0; b < 8; b++)
        #pragma unroll
        for (int a = 6; a >= 0; a--) m[a][b] += m[a + 1][b];

    // JP 2-D prefix of jw
    float j[8][8];
    #pragma unroll
    for (int a = 0; a < 8; a++)
        #pragma unroll
        for (int b = 0; b < 8; b++)
            j[a][b] = jw[(a * 8 + b) * ss + base];
    #pragma unroll
    for (int a = 0; a < 8; a++)
        #pragma unroll
        for (int b = 1; b < 8; b++) j[a][b] += j[a][b - 1];
    #pragma unroll
    for (int b = 0; b < 8; b++)
        #pragma unroll
        for (int a = 1; a < 8; a++) j[a][b] += j[a - 1][b];

    // WC[cx][cy] = (1-a)*MS[ax][ay] + a*JP[jx][jy]
    for (int cx = 0; cx < 15; cx++) {
        int ax = cx < 8 ? 0 : cx - 7;
        int jx = cx < 8 ? cx : 7;
        for (int cy = 0; cy < 15; cy++) {
            int ay = cy < 8 ? 0 : cy - 7;
            int jy = cy < 8 ? cy : 7;
            WC[(cx * 15 + cy) * ss + base] =
                (1.0f - ALPHA) * m[ax][ay] + ALPHA * j[jx][jy];
        }
    }
}

// ---------------- GEMM core: [64 x FIN] * [FIN x 128] ----------------
// 256 threads, thread tile 4(m) x 8(g).
template <int FIN>
__device__ __forceinline__ void gemm_core(const float* __restrict__ Xtile,
                                          const float* __restrict__ W,
                                          float (&acc)[4][8])
{
    __shared__ float Xs[16][68];   // [k][m], stride 68 avoids STS conflicts, 272B rows stay 16B-aligned
    __shared__ float Ws[16][128];  // [k][g]
    int tid = threadIdx.x;
    int tx = tid & 15, ty = tid >> 4;
    int lm = tid >> 2, lk = (tid & 3) * 4;
    int wk = tid >> 4, wg = (tid & 15) * 8;

    for (int k0 = 0; k0 < FIN; k0 += 16) {
        float4 xv = *(const float4*)(Xtile + lm * FIN + k0 + lk);
        float4 w0 = *(const float4*)(W + (k0 + wk) * FOUT + wg);
        float4 w1 = *(const float4*)(W + (k0 + wk) * FOUT + wg + 4);
        __syncthreads();
        Xs[lk + 0][lm] = xv.x; Xs[lk + 1][lm] = xv.y;
        Xs[lk + 2][lm] = xv.z; Xs[lk + 3][lm] = xv.w;
        *(float4*)&Ws[wk][wg]     = w0;
        *(float4*)&Ws[wk][wg + 4] = w1;
        __syncthreads();
        #pragma unroll
        for (int kk = 0; kk < 16; kk++) {
            float4 av = *(const float4*)&Xs[kk][ty * 4];
            float4 b0 = *(const float4*)&Ws[kk][tx * 8];
            float4 b1 = *(const float4*)&Ws[kk][tx * 8 + 4];
            float a_[4] = {av.x, av.y, av.z, av.w};
            float b_[8] = {b0.x, b0.y, b0.z, b0.w, b1.x, b1.y, b1.z, b1.w};
            #pragma unroll
            for (int i = 0; i < 4; i++)
                #pragma unroll
                for (int jj = 0; jj < 8; jj++)
                    acc[i][jj] += a_[i] * b_[jj];
        }
    }
}

__device__ __forceinline__ void store_tile(float* __restrict__ dst, float (&acc)[4][8])
{
    int tx = threadIdx.x & 15, ty = threadIdx.x >> 4;
    #pragma unroll
    for (int i = 0; i < 4; i++) {
        float4 v0 = make_float4(acc[i][0], acc[i][1], acc[i][2], acc[i][3]);
        float4 v1 = make_float4(acc[i][4], acc[i][5], acc[i][6], acc[i][7]);
        *(float4*)(dst + (ty * 4 + i) * FOUT + tx * 8)     = v0;
        *(float4*)(dst + (ty * 4 + i) * FOUT + tx * 8 + 4) = v1;
    }
}

// ---------------- strip / corner GEMM kernels ----------------
template <int FIN>
__global__ void __launch_bounds__(256) gemmG_k(const float* __restrict__ Xt,
                                               const float* __restrict__ MRS,
                                               float* __restrict__ G)
{
    int a = blockIdx.x >> 5, Y = blockIdx.x & 31;         // 224 blocks, a<7
    int q = Y > 24 ? Y - 24 : 0;
    float acc[4][8] = {};
    gemm_core<FIN>(Xt + (size_t)((a + 24) * S + Y) * BATCH * FIN,
                   MRS + (size_t)(a * 8 + q) * FIN * FOUT, acc);
    store_tile(G + (size_t)blockIdx.x * BATCH * FOUT, acc);
}

template <int FIN>
__global__ void __launch_bounds__(256) gemmCG_k(const float* __restrict__ Xt,
                                                const float* __restrict__ MCS,
                                                float* __restrict__ CG)
{
    int b = blockIdx.x >> 5, X = blockIdx.x & 31;         // 224 blocks, b<7
    int p = X > 24 ? X - 24 : 0;
    float acc[4][8] = {};
    gemm_core<FIN>(Xt + (size_t)(X * S + b + 24) * BATCH * FIN,
                   MCS + (size_t)(p * 8 + b) * FIN * FOUT, acc);
    store_tile(CG + (size_t)blockIdx.x * BATCH * FOUT, acc);
}

template <int FIN>
__global__ void __launch_bounds__(256) gemmH_k(const float* __restrict__ Xt,
                                               const float* __restrict__ mw,
                                               float* __restrict__ H)
{
    int a = blockIdx.x / 7, b = blockIdx.x % 7;           // 49 blocks
    float acc[4][8] = {};
    gemm_core<FIN>(Xt + (size_t)((a + 24) * S + b + 24) * BATCH * FIN,
                   mw + (size_t)(a * 8 + b) * FIN * FOUT, acc);
    store_tile(H + (size_t)blockIdx.x * BATCH * FOUT, acc);
}

// ---------------- prefix passes ----------------
__global__ void prefix_rows_k(float* __restrict__ buf)   // over a for [7][32][8192]
{
    int t = blockIdx.x * blockDim.x + threadIdx.x;       // 32*8192 threads
    int yy = t >> 13, mg = t & 8191;
    float run = 0.f;
    #pragma unroll
    for (int a = 0; a < 7; a++) {
        int idx = (a * 32 + yy) * 8192 + mg;
        run += buf[idx];
        buf[idx] = run;
    }
}

__global__ void prefixH_k(float* __restrict__ H)         // 2-D prefix over [7][7][8192]
{
    int mg = blockIdx.x * blockDim.x + threadIdx.x;      // 8192 threads
    float colA[7];
    #pragma unroll
    for (int b = 0; b < 7; b++) colA[b] = 0.f;
    #pragma unroll
    for (int a = 0; a < 7; a++) {
        float run = 0.f;
        #pragma unroll
        for (int b = 0; b < 7; b++) {
            int idx = (a * 7 + b) * 8192 + mg;
            run += H[idx];
            colA[b] += run;
            H[idx] = colA[b];
        }
    }
}

// ---------------- combine: pointwise GEMM + strip adds + bias + leaky ----------------
template <int FIN>
__global__ void __launch_bounds__(256) combine_k(
    const float* __restrict__ Xt, const float* __restrict__ WC,
    const float* __restrict__ Gc, const float* __restrict__ CGc,
    const float* __restrict__ Hc, const float* __restrict__ mb,
    const float* __restrict__ jb, float* __restrict__ Yout)
{
    int p = blockIdx.x;
    int X = p >> 5, Y = p & 31;
    int cx = X <= 24 ? (X < 7 ? X : 7) : X - 17;
    int cy = Y <= 24 ? (Y < 7 ? Y : 7) : Y - 17;

    float acc[4][8] = {};
    gemm_core<FIN>(Xt + (size_t)p * BATCH * FIN,
                   WC + (size_t)(cx * 15 + cy) * FIN * FOUT, acc);

    int tx = threadIdx.x & 15, ty = threadIdx.x >> 4;
    int off = (ty * 4) * FOUT + tx * 8;
    const float ms = 1.0f - ALPHA;

    if (X >= 25) {
        const float* Gp = Gc + (size_t)((X - 25) * S + Y) * BATCH * FOUT + off;
        #pragma unroll
        for (int i = 0; i < 4; i++)
            #pragma unroll
            for (int jj = 0; jj < 8; jj++)
                acc[i][jj] += ms * Gp[i * FOUT + jj];
    }
    if (Y >= 25) {
        const float* Cp = CGc + (size_t)((Y - 25) * S + X) * BATCH * FOUT + off;
        #pragma unroll
        for (int i = 0; i < 4; i++)
            #pragma unroll
            for (int jj = 0; jj < 8; jj++)
                acc[i][jj] += ms * Cp[i * FOUT + jj];
    }
    if (X >= 25 && Y >= 25) {
        const float* Hp = Hc + (size_t)((X - 25) * 7 + (Y - 25)) * BATCH * FOUT + off;
        #pragma unroll
        for (int i = 0; i < 4; i++)
            #pragma unroll
            for (int jj = 0; jj < 8; jj++)
                acc[i][jj] += ms * Hp[i * FOUT + jj];
    }

    float bias[8];
    #pragma unroll
    for (int jj = 0; jj < 8; jj++)
        bias[jj] = ms * mb[tx * 8 + jj] + ALPHA * jb[tx * 8 + jj];

    float* O = Yout + (size_t)p * BATCH * FOUT + off;
    #pragma unroll
    for (int i = 0; i < 4; i++) {
        float v[8];
        #pragma unroll
        for (int jj = 0; jj < 8; jj++) {
            float t = acc[i][jj] + bias[jj];
            v[jj] = t > 0.f ? t : SLOPE * t;
        }
        *(float4*)(O + i * FOUT)     = make_float4(v[0], v[1], v[2], v[3]);
        *(float4*)(O + i * FOUT + 4) = make_float4(v[4], v[5], v[6], v[7]);
    }
}

// ---------------- host launch ----------------
extern "C" void kernel_launch(void* const* d_in, const int* in_sizes, int n_in,
                              void* d_out, int out_size)
{
    const float* x   = (const float*)d_in[0];
    const float* mw0 = (const float*)d_in[5];
    const float* mb0 = (const float*)d_in[6];
    const float* jw0 = (const float*)d_in[7];
    const float* jb0 = (const float*)d_in[8];
    const float* mw1 = (const float*)d_in[9];
    const float* mb1 = (const float*)d_in[10];
    const float* jw1 = (const float*)d_in[11];
    const float* jb1 = (const float*)d_in[12];
    float* out = (float*)d_out;

    float *Xt0, *Yt, *Yt2, *WC, *MRS, *MCS, *G, *CG, *H;
    cudaGetSymbolAddress((void**)&Xt0, d_Xt0);
    cudaGetSymbolAddress((void**)&Yt,  d_Yt);
    cudaGetSymbolAddress((void**)&Yt2, d_Yt2);
    cudaGetSymbolAddress((void**)&WC,  d_WC);
    cudaGetSymbolAddress((void**)&MRS, d_MRS);
    cudaGetSymbolAddress((void**)&MCS, d_MCS);
    cudaGetSymbolAddress((void**)&G,   d_G);
    cudaGetSymbolAddress((void**)&CG,  d_CG);
    cudaGetSymbolAddress((void**)&H,   d_H);

    dim3 tb(32, 8);
    // x [64*64][1024] -> Xt0 [1024][64*64]
    transpose_k<<<dim3(1024 / 32, 4096 / 32), tb>>>(Xt0, x, 4096, 1024);

    // ---- layer 0: Fin = 64 ----
    prep_k<<<(64 * 128) / 256, 256>>>(mw0, jw0, WC, MRS, MCS, 64);
    gemmG_k<64><<<224, 256>>>(Xt0, MRS, G);
    gemmCG_k<64><<<224, 256>>>(Xt0, MCS, CG);
    gemmH_k<64><<<49, 256>>>(Xt0, mw0, H);
    prefix_rows_k<<<1024, 256>>>(G);
    prefix_rows_k<<<1024, 256>>>(CG);
    prefixH_k<<<32, 256>>>(H);
    combine_k<64><<<1024, 256>>>(Xt0, WC, G, CG, H, mb0, jb0, Yt);

    // ---- layer 1: Fin = 128 ----
    prep_k<<<(128 * 128) / 256, 256>>>(mw1, jw1, WC, MRS, MCS, 128);
    gemmG_k<128><<<224, 256>>>(Yt, MRS, G);
    gemmCG_k<128><<<224, 256>>>(Yt, MCS, CG);
    gemmH_k<128><<<49, 256>>>(Yt, mw1, H);
    prefix_rows_k<<<1024, 256>>>(G);
    prefix_rows_k<<<1024, 256>>>(CG);
    prefixH_k<<<32, 256>>>(H);
    combine_k<128><<<1024, 256>>>(Yt, WC, G, CG, H, mb1, jb1, Yt2);

    // Yt2 [1024][8192] -> out [8192][1024]
    transpose_k<<<dim3(8192 / 32, 1024 / 32), tb>>>(out, Yt2, 1024, 8192);
}

// round 2
// speedup vs baseline: 1.2180x; 1.2180x over previous
#include <cuda_runtime.h>

// LatticeCNN on GB300 — closed-form lattice conv decomposition + f32x2 packed FMA.
//
// join conv  == pointwise with 2-D prefix-summed weights
// meet conv  == pointwise(suffix weights) + x-prefix row strips + y-prefix col
//               strips + 2-D-prefix corner term
//
// Per layer: 1521 GEMM units [64 x Fin] * [Fin x 128] + elementwise prefixes.
// GEMM inner loop uses fma.rn.f32x2 (2 MAC/issue on the FMA pipe).

#define ALPHA  0.5f
#define SLOPE  0.01f
#define BATCH  64
#define S      32
#define NPIX   1024
#define FOUT   128

typedef unsigned long long u64;

__device__ __forceinline__ u64 pack2s(float x) {
    u64 r; asm("mov.b64 %0, {%1, %1};" : "=l"(r) : "f"(x)); return r;
}
__device__ __forceinline__ u64 pack2(float x, float y) {
    u64 r; asm("mov.b64 %0, {%1, %2};" : "=l"(r) : "f"(x), "f"(y)); return r;
}
__device__ __forceinline__ float2 unpk(u64 v) {
    float2 r; asm("mov.b64 {%0, %1}, %2;" : "=f"(r.x), "=f"(r.y) : "l"(v)); return r;
}
__device__ __forceinline__ void fma2(u64& d, u64 a, u64 b) {
    asm("fma.rn.f32x2 %0, %1, %2, %0;" : "+l"(d) : "l"(a), "l"(b));
}
__device__ __forceinline__ void add2(u64& d, u64 a) {
    asm("add.rn.f32x2 %0, %1, %0;" : "+l"(d) : "l"(a));
}

// ---------------- device scratch (no allocation allowed) ----------------
__device__ float d_Xt0[NPIX * BATCH * 64];    // layer0 input, pixel-major
__device__ float d_Yt [NPIX * BATCH * 128];   // layer0 output / layer1 input
__device__ float d_Yt2[NPIX * BATCH * 128];   // layer1 output (pixel-major)
__device__ float d_WC [225 * 128 * FOUT];     // combined pointwise weights (15x15 classes)
__device__ float d_MRS[64 * 128 * FOUT];      // row-suffix weights  MRS[a][q]
__device__ float d_MCS[64 * 128 * FOUT];      // col-suffix weights  MCS[p][b]
__device__ float d_G  [224 * BATCH * FOUT];   // row strip tiles  G[a][y]
__device__ float d_CG [224 * BATCH * FOUT];   // col strip tiles  CG[b][x]
__device__ float d_H  [49  * BATCH * FOUT];   // corner tiles     H[a][b]

// ---------------- tiled transpose: dst[C][R] = src[R][C] ----------------
__global__ void transpose_k(float* __restrict__ dst, const float* __restrict__ src,
                            int R, int C)
{
    __shared__ float tile[32][33];
    int c0 = blockIdx.x * 32;
    int r0 = blockIdx.y * 32;
    #pragma unroll
    for (int i = 0; i < 4; i++)
        tile[threadIdx.y + 8 * i][threadIdx.x] =
            src[(size_t)(r0 + threadIdx.y + 8 * i) * C + c0 + threadIdx.x];
    __syncthreads();
    #pragma unroll
    for (int i = 0; i < 4; i++)
        dst[(size_t)(c0 + threadIdx.y + 8 * i) * R + r0 + threadIdx.x] =
            tile[threadIdx.x][threadIdx.y + 8 * i];
}

// ---------------- per-layer weight-table prep ----------------
__global__ void prep_k(const float* __restrict__ mw, const float* __restrict__ jw,
                       float* __restrict__ WC, float* __restrict__ MRS,
                       float* __restrict__ MCS, int Fin)
{
    int idx = blockIdx.x * blockDim.x + threadIdx.x;
    if (idx >= Fin * FOUT) return;
    int base = idx;              // = f*FOUT + g
    int ss = Fin * FOUT;

    float m[8][8];
    #pragma unroll
    for (int a = 0; a < 8; a++)
        #pragma unroll
        for (int b = 0; b < 8; b++)
            m[a][b] = mw[(a * 8 + b) * ss + base];

    // MCS[p][b] = sum_{a>=p} mw[a][b]
    {
        float col[8];
        #pragma unroll
        for (int b = 0; b < 8; b++) col[b] = 0.f;
        #pragma unroll
        for (int p = 7; p >= 0; p--)
            #pragma unroll
            for (int b = 0; b < 8; b++) {
                col[b] += m[p][b];
                MCS[(p * 8 + b) * ss + base] = col[b];
            }
    }
    // row suffix in place -> MRS[a][q] = sum_{b>=q} mw[a][b]
    #pragma unroll
    for (int a = 0; a < 8; a++) {
        #pragma unroll
        for (int q = 6; q >= 0; q--) m[a][q] += m[a][q + 1];
        #pragma unroll
        for (int q = 0; q < 8; q++) MRS[(a * 8 + q) * ss + base] = m[a][q];
    }
    // col suffix in place -> m = MS 2-D suffix table
    #pragma unroll
    for (int b = 0; b < 8; b++)
        #pragma unroll
        for (int a = 6; a >= 0; a--) m[a][b] += m[a + 1][b];

    // JP 2-D prefix of jw
    float j[8][8];
    #pragma unroll
    for (int a = 0; a < 8; a++)
        #pragma unroll
        for (int b = 0; b < 8; b++)
            j[a][b] = jw[(a * 8 + b) * ss + base];
    #pragma unroll
    for (int a = 0; a < 8; a++)
        #pragma unroll
        for (int b = 1; b < 8; b++) j[a][b] += j[a][b - 1];
    #pragma unroll
    for (int b = 0; b < 8; b++)
        #pragma unroll
        for (int a = 1; a < 8; a++) j[a][b] += j[a - 1][b];

    // WC[cx][cy] = (1-a)*MS[ax][ay] + a*JP[jx][jy]
    for (int cx = 0; cx < 15; cx++) {
        int ax = cx < 8 ? 0 : cx - 7;
        int jx = cx < 8 ? cx : 7;
        for (int cy = 0; cy < 15; cy++) {
            int ay = cy < 8 ? 0 : cy - 7;
            int jy = cy < 8 ? cy : 7;
            WC[(cx * 15 + cy) * ss + base] =
                (1.0f - ALPHA) * m[ax][ay] + ALPHA * j[jx][jy];
        }
    }
}

// ---------------- GEMM core: [64 x FIN] * [FIN x 128], f32x2, double-buffered ----
// 256 threads, thread tile 4(m) x 8(g) -> acc[4][4] packed pairs along g.
template <int FIN>
__device__ __forceinline__ void gemm_core(const float* __restrict__ Xtile,
                                          const float* __restrict__ W,
                                          u64 (&acc)[4][4])
{
    __shared__ __align__(16) float Xs[2][16][68];
    __shared__ __align__(16) float Ws[2][16][128];
    const int tid = threadIdx.x;
    const int tx = tid & 15, ty = tid >> 4;
    const int lm = tid >> 2, lk = (tid & 3) * 4;
    const int wk = tid >> 4, wg = (tid & 15) * 8;
    constexpr int NC = FIN / 16;

    float4 xv = *(const float4*)(Xtile + lm * FIN + lk);
    float4 w0 = *(const float4*)(W + wk * FOUT + wg);
    float4 w1 = *(const float4*)(W + wk * FOUT + wg + 4);
    Xs[0][lk + 0][lm] = xv.x; Xs[0][lk + 1][lm] = xv.y;
    Xs[0][lk + 2][lm] = xv.z; Xs[0][lk + 3][lm] = xv.w;
    *(float4*)&Ws[0][wk][wg]     = w0;
    *(float4*)&Ws[0][wk][wg + 4] = w1;
    __syncthreads();

    #pragma unroll
    for (int c = 0; c < NC; c++) {
        const int cb = c & 1;
        if (c + 1 < NC) {
            xv = *(const float4*)(Xtile + lm * FIN + (c + 1) * 16 + lk);
            w0 = *(const float4*)(W + ((c + 1) * 16 + wk) * FOUT + wg);
            w1 = *(const float4*)(W + ((c + 1) * 16 + wk) * FOUT + wg + 4);
        }
        #pragma unroll
        for (int kk = 0; kk < 16; kk++) {
            float4 av = *(const float4*)&Xs[cb][kk][ty * 4];
            ulonglong2 b0 = *(const ulonglong2*)&Ws[cb][kk][tx * 8];
            ulonglong2 b1 = *(const ulonglong2*)&Ws[cb][kk][tx * 8 + 4];
            u64 a0 = pack2s(av.x), a1 = pack2s(av.y);
            u64 a2 = pack2s(av.z), a3 = pack2s(av.w);
            fma2(acc[0][0], a0, b0.x); fma2(acc[0][1], a0, b0.y);
            fma2(acc[0][2], a0, b1.x); fma2(acc[0][3], a0, b1.y);
            fma2(acc[1][0], a1, b0.x); fma2(acc[1][1], a1, b0.y);
            fma2(acc[1][2], a1, b1.x); fma2(acc[1][3], a1, b1.y);
            fma2(acc[2][0], a2, b0.x); fma2(acc[2][1], a2, b0.y);
            fma2(acc[2][2], a2, b1.x); fma2(acc[2][3], a2, b1.y);
            fma2(acc[3][0], a3, b0.x); fma2(acc[3][1], a3, b0.y);
            fma2(acc[3][2], a3, b1.x); fma2(acc[3][3], a3, b1.y);
        }
        if (c + 1 < NC) {
            Xs[cb ^ 1][lk + 0][lm] = xv.x; Xs[cb ^ 1][lk + 1][lm] = xv.y;
            Xs[cb ^ 1][lk + 2][lm] = xv.z; Xs[cb ^ 1][lk + 3][lm] = xv.w;
            *(float4*)&Ws[cb ^ 1][wk][wg]     = w0;
            *(float4*)&Ws[cb ^ 1][wk][wg + 4] = w1;
            __syncthreads();
        }
    }
}

__device__ __forceinline__ void store_tile(float* __restrict__ dst, u64 (&acc)[4][4])
{
    int tx = threadIdx.x & 15, ty = threadIdx.x >> 4;
    #pragma unroll
    for (int i = 0; i < 4; i++) {
        float2 p0 = unpk(acc[i][0]), p1 = unpk(acc[i][1]);
        float2 p2 = unpk(acc[i][2]), p3 = unpk(acc[i][3]);
        *(float4*)(dst + (ty * 4 + i) * FOUT + tx * 8)     = make_float4(p0.x, p0.y, p1.x, p1.y);
        *(float4*)(dst + (ty * 4 + i) * FOUT + tx * 8 + 4) = make_float4(p2.x, p2.y, p3.x, p3.y);
    }
}

// ---------------- fused strip / corner GEMM kernel (497 blocks) ----------------
template <int FIN>
__global__ void __launch_bounds__(256) strips_k(
    const float* __restrict__ Xt, const float* __restrict__ MRS,
    const float* __restrict__ MCS, const float* __restrict__ mw,
    float* __restrict__ G, float* __restrict__ CG, float* __restrict__ H)
{
    int bid = blockIdx.x;
    const float* Xtile; const float* W; float* dst;
    if (bid < 224) {
        int a = bid >> 5, Y = bid & 31;
        int q = Y > 24 ? Y - 24 : 0;
        Xtile = Xt + (size_t)((a + 24) * S + Y) * BATCH * FIN;
        W = MRS + (size_t)(a * 8 + q) * FIN * FOUT;
        dst = G + (size_t)bid * BATCH * FOUT;
    } else if (bid < 448) {
        int t = bid - 224;
        int b = t >> 5, X = t & 31;
        int p = X > 24 ? X - 24 : 0;
        Xtile = Xt + (size_t)(X * S + b + 24) * BATCH * FIN;
        W = MCS + (size_t)(p * 8 + b) * FIN * FOUT;
        dst = CG + (size_t)t * BATCH * FOUT;
    } else {
        int t = bid - 448;
        int a = t / 7, b = t % 7;
        Xtile = Xt + (size_t)((a + 24) * S + b + 24) * BATCH * FIN;
        W = mw + (size_t)(a * 8 + b) * FIN * FOUT;
        dst = H + (size_t)t * BATCH * FOUT;
    }
    u64 acc[4][4] = {};
    gemm_core<FIN>(Xtile, W, acc);
    store_tile(dst, acc);
}

// ---------------- prefix passes ----------------
__global__ void prefix_rows2_k(float* __restrict__ G, float* __restrict__ CG)
{
    int t = blockIdx.x * blockDim.x + threadIdx.x;       // 2 * 32*8192 threads
    float* buf = (t < 32 * 8192) ? G : CG;
    int tt = t & (32 * 8192 - 1);
    int yy = tt >> 13, mg = tt & 8191;
    float run = 0.f;
    #pragma unroll
    for (int a = 0; a < 7; a++) {
        int idx = (a * 32 + yy) * 8192 + mg;
        run += buf[idx];
        buf[idx] = run;
    }
}

__global__ void prefixH_k(float* __restrict__ H)         // 2-D prefix over [7][7][8192]
{
    int mg = blockIdx.x * blockDim.x + threadIdx.x;      // 8192 threads
    float colA[7];
    #pragma unroll
    for (int b = 0; b < 7; b++) colA[b] = 0.f;
    #pragma unroll
    for (int a = 0; a < 7; a++) {
        float run = 0.f;
        #pragma unroll
        for (int b = 0; b < 7; b++) {
            int idx = (a * 7 + b) * 8192 + mg;
            run += H[idx];
            colA[b] += run;
            H[idx] = colA[b];
        }
    }
}

// ---------------- combine: pointwise GEMM + strip adds + bias + leaky ----------------
template <int FIN>
__global__ void __launch_bounds__(256) combine_k(
    const float* __restrict__ Xt, const float* __restrict__ WC,
    const float* __restrict__ Gc, const float* __restrict__ CGc,
    const float* __restrict__ Hc, const float* __restrict__ mb,
    const float* __restrict__ jb, float* __restrict__ Yout)
{
    int p = blockIdx.x;
    int X = p >> 5, Y = p & 31;
    int cx = X <= 24 ? (X < 7 ? X : 7) : X - 17;
    int cy = Y <= 24 ? (Y < 7 ? Y : 7) : Y - 17;

    u64 acc[4][4] = {};
    gemm_core<FIN>(Xt + (size_t)p * BATCH * FIN,
                   WC + (size_t)(cx * 15 + cy) * FIN * FOUT, acc);

    int tx = threadIdx.x & 15, ty = threadIdx.x >> 4;
    int off = (ty * 4) * FOUT + tx * 8;
    const float ms = 1.0f - ALPHA;
    const u64 ms2 = pack2s(ms);

    if (X >= 25) {
        const float* Gp = Gc + (size_t)((X - 25) * S + Y) * BATCH * FOUT + off;
        #pragma unroll
        for (int i = 0; i < 4; i++) {
            const ulonglong2 g0 = *(const ulonglong2*)(Gp + i * FOUT);
            const ulonglong2 g1 = *(const ulonglong2*)(Gp + i * FOUT + 4);
            fma2(acc[i][0], ms2, g0.x); fma2(acc[i][1], ms2, g0.y);
            fma2(acc[i][2], ms2, g1.x); fma2(acc[i][3], ms2, g1.y);
        }
    }
    if (Y >= 25) {
        const float* Cp = CGc + (size_t)((Y - 25) * S + X) * BATCH * FOUT + off;
        #pragma unroll
        for (int i = 0; i < 4; i++) {
            const ulonglong2 g0 = *(const ulonglong2*)(Cp + i * FOUT);
            const ulonglong2 g1 = *(const ulonglong2*)(Cp + i * FOUT + 4);
            fma2(acc[i][0], ms2, g0.x); fma2(acc[i][1], ms2, g0.y);
            fma2(acc[i][2], ms2, g1.x); fma2(acc[i][3], ms2, g1.y);
        }
    }
    if (X >= 25 && Y >= 25) {
        const float* Hp = Hc + (size_t)((X - 25) * 7 + (Y - 25)) * BATCH * FOUT + off;
        #pragma unroll
        for (int i = 0; i < 4; i++) {
            const ulonglong2 g0 = *(const ulonglong2*)(Hp + i * FOUT);
            const ulonglong2 g1 = *(const ulonglong2*)(Hp + i * FOUT + 4);
            fma2(acc[i][0], ms2, g0.x); fma2(acc[i][1], ms2, g0.y);
            fma2(acc[i][2], ms2, g1.x); fma2(acc[i][3], ms2, g1.y);
        }
    }

    u64 bias2[4];
    #pragma unroll
    for (int jj = 0; jj < 4; jj++) {
        int g = tx * 8 + jj * 2;
        bias2[jj] = pack2(ms * mb[g]     + ALPHA * jb[g],
                          ms * mb[g + 1] + ALPHA * jb[g + 1]);
    }

    float* O = Yout + (size_t)p * BATCH * FOUT + off;
    #pragma unroll
    for (int i = 0; i < 4; i++) {
        add2(acc[i][0], bias2[0]); add2(acc[i][1], bias2[1]);
        add2(acc[i][2], bias2[2]); add2(acc[i][3], bias2[3]);
        float2 p0 = unpk(acc[i][0]), p1 = unpk(acc[i][1]);
        float2 p2 = unpk(acc[i][2]), p3 = unpk(acc[i][3]);
        float v[8] = {p0.x, p0.y, p1.x, p1.y, p2.x, p2.y, p3.x, p3.y};
        #pragma unroll
        for (int jj = 0; jj < 8; jj++)
            v[jj] = fmaxf(v[jj], SLOPE * v[jj]);
        *(float4*)(O + i * FOUT)     = make_float4(v[0], v[1], v[2], v[3]);
        *(float4*)(O + i * FOUT + 4) = make_float4(v[4], v[5], v[6], v[7]);
    }
}

// ---------------- host launch ----------------
extern "C" void kernel_launch(void* const* d_in, const int* in_sizes, int n_in,
                              void* d_out, int out_size)
{
    const float* x   = (const float*)d_in[0];
    const float* mw0 = (const float*)d_in[5];
    const float* mb0 = (const float*)d_in[6];
    const float* jw0 = (const float*)d_in[7];
    const float* jb0 = (const float*)d_in[8];
    const float* mw1 = (const float*)d_in[9];
    const float* mb1 = (const float*)d_in[10];
    const float* jw1 = (const float*)d_in[11];
    const float* jb1 = (const float*)d_in[12];
    float* out = (float*)d_out;

    float *Xt0, *Yt, *Yt2, *WC, *MRS, *MCS, *G, *CG, *H;
    cudaGetSymbolAddress((void**)&Xt0, d_Xt0);
    cudaGetSymbolAddress((void**)&Yt,  d_Yt);
    cudaGetSymbolAddress((void**)&Yt2, d_Yt2);
    cudaGetSymbolAddress((void**)&WC,  d_WC);
    cudaGetSymbolAddress((void**)&MRS, d_MRS);
    cudaGetSymbolAddress((void**)&MCS, d_MCS);
    cudaGetSymbolAddress((void**)&G,   d_G);
    cudaGetSymbolAddress((void**)&CG,  d_CG);
    cudaGetSymbolAddress((void**)&H,   d_H);

    dim3 tb(32, 8);
    // x [64*64][1024] -> Xt0 [1024][64*64]
    transpose_k<<<dim3(1024 / 32, 4096 / 32), tb>>>(Xt0, x, 4096, 1024);

    // ---- layer 0: Fin = 64 ----
    prep_k<<<(64 * 128) / 256, 256>>>(mw0, jw0, WC, MRS, MCS, 64);
    strips_k<64><<<497, 256>>>(Xt0, MRS, MCS, mw0, G, CG, H);
    prefix_rows2_k<<<2048, 256>>>(G, CG);
    prefixH_k<<<32, 256>>>(H);
    combine_k<64><<<1024, 256>>>(Xt0, WC, G, CG, H, mb0, jb0, Yt);

    // ---- layer 1: Fin = 128 ----
    prep_k<<<(128 * 128) / 256, 256>>>(mw1, jw1, WC, MRS, MCS, 128);
    strips_k<128><<<497, 256>>>(Yt, MRS, MCS, mw1, G, CG, H);
    prefix_rows2_k<<<2048, 256>>>(G, CG);
    prefixH_k<<<32, 256>>>(H);
    combine_k<128><<<1024, 256>>>(Yt, WC, G, CG, H, mb1, jb1, Yt2);

    // Yt2 [1024][8192] -> out [8192][1024]
    transpose_k<<<dim3(8192 / 32, 1024 / 32), tb>>>(out, Yt2, 1024, 8192);
}